// round 15
// baseline (speedup 1.0000x reference)
#include <cuda_runtime.h>
#include <cstdint>

#define BATCH 8
#define NPRI 57744
#define NCLS 81
#define NOBJ 20
#define ROWS (BATCH * NPRI)   // 461952 = 64 * 7218
#define CHUNK 64
#define NBINS (1u << 20)
#define EQCAP 8192
#define MINEBLKS 226

#define NEGINF __int_as_float(0xff800000)

// ---------------- device scratch ----------------
__device__ unsigned long long g_bestPrior[BATCH * NOBJ];
__device__ float    g_bto[ROWS];
__device__ int      g_bti[ROWS];
__device__ unsigned g_keys[ROWS];
__device__ unsigned g_posList[ROWS];      // (ct<<20)|row
__device__ unsigned long long g_eq[EQCAP];// (key<<32)|~row
__device__ unsigned g_hist[NBINS];        // 4 MB, 20-bit key histogram
__device__ unsigned g_histC[256];         // coarse 8-bit histogram
__device__ float    g_sl1, g_cepos, g_cenegsum;
__device__ unsigned g_numpos, g_negcnt, g_bhi, g_take, g_takeAll, g_eqcnt;

// ---------------- helpers ----------------
__device__ __forceinline__ float wmaxf(float v) {
    #pragma unroll
    for (int o = 16; o; o >>= 1) v = fmaxf(v, __shfl_xor_sync(0xffffffffu, v, o));
    return v;
}
__device__ __forceinline__ float wsumf(float v) {
    #pragma unroll
    for (int o = 16; o; o >>= 1) v += __shfl_xor_sync(0xffffffffu, v, o);
    return v;
}
__device__ __forceinline__ unsigned f2key(float f) {
    unsigned u = __float_as_uint(f);
    return (u & 0x80000000u) ? ~u : (u | 0x80000000u);
}
__device__ __forceinline__ float warp_lse(const float* __restrict__ cr, int lane,
                                          float& v0_lane0) {
    float v0 = cr[lane];
    float v1 = cr[lane + 32];
    float v2 = (lane < 17) ? cr[lane + 64] : NEGINF;
    float mAll = wmaxf(fmaxf(fmaxf(v0, v1), v2));
    float e2 = __expf(v0 - mAll) + __expf(v1 - mAll) +
               ((lane < 17) ? __expf(v2 - mAll) : 0.f);
    v0_lane0 = __shfl_sync(0xffffffffu, v0, 0);
    return mAll + __logf(wsumf(e2));
}

// ---------------- kernels ----------------
__global__ void k_init() {
    int t = threadIdx.x;
    if (t < BATCH * NOBJ) g_bestPrior[t] = 0ull;
    if (t == 0) {
        g_sl1 = 0.f; g_cepos = 0.f; g_cenegsum = 0.f;
        g_numpos = 0u; g_negcnt = 0u; g_bhi = 0u;
        g_take = 0u; g_takeAll = 0u; g_eqcnt = 0u;
    }
}

// per-GT best prior AND per-prior best overlap/idx stores
__global__ void k_match(const float* __restrict__ priors,
                        const float* __restrict__ gt_boxes) {
    int b = blockIdx.y;
    int p = blockIdx.x * blockDim.x + threadIdx.x;
    __shared__ float4 sgt[NOBJ];
    __shared__ float  sga[NOBJ];
    __shared__ unsigned long long sbest[NOBJ];
    if (threadIdx.x < NOBJ) {
        float4 g = ((const float4*)gt_boxes)[b * NOBJ + threadIdx.x];
        sgt[threadIdx.x] = g;
        sga[threadIdx.x] = (g.z - g.x) * (g.w - g.y);
        sbest[threadIdx.x] = 0ull;
    }
    __syncthreads();

    if (p < NPRI) {
        float4 pr = ((const float4*)priors)[p];
        float px1 = pr.x - pr.z * 0.5f, py1 = pr.y - pr.w * 0.5f;
        float px2 = pr.x + pr.z * 0.5f, py2 = pr.y + pr.w * 0.5f;
        float pa = pr.z * pr.w;
        float bestOv = -1.f; int bestN = 0;
        #pragma unroll
        for (int n = 0; n < NOBJ; n++) {
            float4 g = sgt[n];
            float ix = fmaxf(fminf(px2, g.z) - fmaxf(px1, g.x), 0.f);
            float iy = fmaxf(fminf(py2, g.w) - fmaxf(py1, g.y), 0.f);
            float inter = ix * iy;
            float iou = inter / (pa + sga[n] - inter);
            if (iou > bestOv) { bestOv = iou; bestN = n; }
            if (iou > 0.f) {
                unsigned long long k =
                    (((unsigned long long)__float_as_uint(iou)) << 32) |
                    (unsigned long long)(~(unsigned)p);
                if (k > sbest[n]) atomicMax(&sbest[n], k);
            }
        }
        g_bto[b * NPRI + p] = bestOv;
        g_bti[b * NPRI + p] = bestN;
    }
    __syncthreads();
    if (threadIdx.x < NOBJ && sbest[threadIdx.x])
        atomicMax(&g_bestPrior[b * NOBJ + threadIdx.x], sbest[threadIdx.x]);
}

// clear histograms + apply force-match overrides (block 0)
__global__ void k_clearhist() {
    unsigned gid = blockIdx.x * blockDim.x + threadIdx.x;
    uint4 z = {0u, 0u, 0u, 0u};
    uint4* h4 = (uint4*)g_hist;
    #pragma unroll
    for (int j = 0; j < 2; j++) {
        unsigned i = gid + j * 131072u;
        if (i < NBINS / 4) h4[i] = z;
    }
    if (gid < 256) g_histC[gid] = 0u;
    if (blockIdx.x == 0 && threadIdx.x < BATCH) {
        int b = threadIdx.x;
        for (int n = 0; n < NOBJ; n++) {   // sequential: last n wins
            unsigned long long v = g_bestPrior[b * NOBJ + n];
            unsigned p = (v == 0ull) ? 0u : ~(unsigned)(v & 0xFFFFFFFFull);
            g_bto[b * NPRI + p] = 2.0f;
            g_bti[b * NPRI + p] = n;
        }
    }
}

// 64 threads = 64 rows; conf staged via cp.async; match results loaded
__global__ void __launch_bounds__(CHUNK)
k_bigpass(const float* __restrict__ loc_data,
          const float* __restrict__ conf,
          const float* __restrict__ priors,
          const float* __restrict__ gt_boxes,
          const int*   __restrict__ gt_labels) {
    __shared__ float s[CHUNK * NCLS];          // 20736 B
    int tid = threadIdx.x;
    int S = blockIdx.x * CHUNK;
    int row = S + tid;

    const float4* c4 = (const float4*)conf + (size_t)S * NCLS / 4;
    unsigned sbase = (unsigned)__cvta_generic_to_shared(s);
    int i = tid;
    #pragma unroll
    for (int k = 0; k < 20; k++, i += CHUNK)   // 20*64 = 1280
        asm volatile("cp.async.cg.shared.global [%0], [%1], 16;"
                     :: "r"(sbase + i * 16), "l"(c4 + i));
    if (tid < 16)                               // + 16 = 1296 = 64*81/4
        asm volatile("cp.async.cg.shared.global [%0], [%1], 16;"
                     :: "r"(sbase + (1280 + tid) * 16), "l"(c4 + 1280 + tid));
    asm volatile("cp.async.commit_group;");

    // prefetch match results while cp.async streams
    float ov = g_bto[row];
    int   n  = g_bti[row];

    asm volatile("cp.async.wait_group 0;");
    __syncthreads();

    const float* rp = s + tid * NCLS;
    float m0 = rp[1], m1 = rp[2], m2 = rp[3], m3 = rp[4];
    #pragma unroll
    for (int c = 5; c <= 77; c += 4) {     // ILP-4 fmax, classes 1..80
        m0 = fmaxf(m0, rp[c]);
        m1 = fmaxf(m1, rp[c + 1]);
        m2 = fmaxf(m2, rp[c + 2]);
        m3 = fmaxf(m3, rp[c + 3]);
    }
    float m = fmaxf(fmaxf(m0, m1), fmaxf(m2, m3));

    int b = row / NPRI;
    int ct;
    if (ov < 0.4f) ct = 0;
    else if (ov < 0.5f) ct = -1;
    else ct = gt_labels[b * NOBJ + n];     // rare path, direct gmem

    unsigned key = 0u;
    if (ct == 0) { key = f2key(m); if (!key) key = 1u; }
    g_keys[row] = key;
    if (key) {
        atomicAdd(&g_hist[key >> 12], 1u);
        atomicAdd(&g_histC[key >> 24], 1u);
    }

    if (ct > 0) {   // rare
        int p = row - b * NPRI;
        float4 pr = ((const float4*)priors)[p];
        float4 g  = ((const float4*)gt_boxes)[b * NOBJ + n];
        float lt[4];
        lt[0] = ((g.x + g.z) * 0.5f - pr.x) / (0.1f * pr.z);
        lt[1] = ((g.y + g.w) * 0.5f - pr.y) / (0.1f * pr.w);
        lt[2] = logf((g.z - g.x) / pr.z) / 0.2f;
        lt[3] = logf((g.w - g.y) / pr.w) / 0.2f;
        const float* ld = loc_data + (size_t)row * 4;
        float sl = 0.f;
        #pragma unroll
        for (int q = 0; q < 4; q++) {
            float d = ld[q] - lt[q];
            float a = fabsf(d);
            sl += (a < 1.f) ? 0.5f * d * d : a - 0.5f;
        }
        atomicAdd(&g_sl1, sl);
        unsigned slot = atomicAdd(&g_numpos, 1u);
        g_posList[slot] = ((unsigned)ct << 20) | (unsigned)row;
    }
}

// one block: coarse scan -> pick coarse bin -> fine scan of its 4096 bins
__global__ void __launch_bounds__(256)
k_select() {
    __shared__ unsigned part[256];
    __shared__ unsigned sCb, sR0;
    int t = threadIdx.x;

    // descending coarse scan (bin 255 first)
    unsigned v = g_histC[255 - t];
    part[t] = v; __syncthreads();
    for (int off = 1; off < 256; off <<= 1) {
        unsigned add = (t >= off) ? part[t - off] : 0u;
        __syncthreads(); part[t] += add; __syncthreads();
    }
    unsigned total = part[255];
    unsigned K = 3u * g_numpos;
    if (K == 0u) { if (t == 0) { g_bhi = NBINS; g_take = 0u; } return; }
    if (total <= K) {
        if (t == 0) { g_takeAll = 1u; g_bhi = NBINS; g_take = 0u; }
        return;
    }
    unsigned incl = part[t], excl = incl - v;
    if (excl < K && K <= incl) { sCb = 255u - (unsigned)t; sR0 = K - excl; }
    __syncthreads();

    // fine scan within coarse bin (4096 fine bins, descending)
    unsigned cb = sCb, r0 = sR0;
    unsigned top = cb * 4096u + 4095u;
    unsigned cnt[16], cs = 0;
    #pragma unroll
    for (int j = 0; j < 16; j++) { cnt[j] = g_hist[top - (t * 16 + j)]; cs += cnt[j]; }
    part[t] = cs; __syncthreads();
    for (int off = 1; off < 256; off <<= 1) {
        unsigned add = (t >= off) ? part[t - off] : 0u;
        __syncthreads(); part[t] += add; __syncthreads();
    }
    unsigned incl2 = part[t], excl2 = incl2 - cs;
    if (excl2 < r0 && r0 <= incl2) {
        unsigned cum = excl2;
        #pragma unroll
        for (int j = 0; j < 16; j++) {
            if (r0 <= cum + cnt[j]) {
                g_bhi = top - (t * 16 + j);
                g_take = r0 - cum;
                break;
            }
            cum += cnt[j];
        }
    }
}

// fused: scan keys, compute neg CE for clear winners, collect boundary,
// plus pos CE (grid-strided)
__global__ void __launch_bounds__(256)
k_mine(const float* __restrict__ conf) {
    __shared__ unsigned list[2048];
    __shared__ unsigned s_cnt;
    __shared__ float s_neg, s_pos;
    int tid = threadIdx.x;
    int lane = tid & 31;
    int warp = tid >> 5;
    if (tid == 0) { s_cnt = 0u; s_neg = 0.f; s_pos = 0.f; }
    __syncthreads();

    unsigned takeAll = g_takeAll;
    unsigned bhi = g_bhi;
    int base = blockIdx.x * 2048;
    #pragma unroll
    for (int j = 0; j < 8; j++) {
        int i = base + j * 256 + tid;
        if (i < ROWS) {
            unsigned key = g_keys[i];
            if (key) {
                unsigned bin = key >> 12;
                if (takeAll || bin > bhi) {
                    unsigned slot = atomicAdd(&s_cnt, 1u);
                    list[slot] = (unsigned)i;
                } else if (bin == bhi) {
                    unsigned slot = atomicAdd(&g_eqcnt, 1u);
                    if (slot < EQCAP)
                        g_eq[slot] = (((unsigned long long)key) << 32) |
                                     (unsigned long long)(~(unsigned)i);
                }
            }
        }
    }
    __syncthreads();

    unsigned cnt = s_cnt;
    float accN = 0.f;
    for (unsigned li = warp; li < cnt; li += 8) {
        int row = (int)list[li];
        float c0;
        float lse = warp_lse(conf + (size_t)row * NCLS, lane, c0);
        if (lane == 0) accN += lse - c0;
    }

    unsigned np = g_numpos;
    float accP = 0.f;
    for (unsigned i = blockIdx.x * 8 + warp; i < np; i += MINEBLKS * 8) {
        unsigned e = g_posList[i];
        int row = (int)(e & 0xFFFFFu);
        int ct  = (int)(e >> 20);
        const float* cr = conf + (size_t)row * NCLS;
        float v0 = cr[lane];
        float v1 = cr[lane + 32];
        float v2 = (lane < 17) ? cr[lane + 64] : NEGINF;
        float mAll = wmaxf(fmaxf(fmaxf(v0, v1), v2));
        float e2 = __expf(v0 - mAll) + __expf(v1 - mAll) +
                   ((lane < 17) ? __expf(v2 - mAll) : 0.f);
        float lse = mAll + __logf(wsumf(e2));
        float x = NEGINF;
        if (lane == ct) x = v0;
        if (lane + 32 == ct) x = v1;
        if (lane < 17 && lane + 64 == ct) x = v2;
        x = wmaxf(x);
        if (lane == 0) accP += lse - x;
    }
    if (lane == 0) {
        if (accN != 0.f) atomicAdd(&s_neg, accN);
        if (accP != 0.f) atomicAdd(&s_pos, accP);
    }
    __syncthreads();
    if (tid == 0) {
        if (cnt) atomicAdd(&g_negcnt, cnt);
        if (s_neg != 0.f) atomicAdd(&g_cenegsum, s_neg);
        if (s_pos != 0.f) atomicAdd(&g_cepos, s_pos);
    }
}

// one block: exact boundary resolution + CE of chosen boundary rows + outputs
__global__ void __launch_bounds__(1024)
k_final(const float* __restrict__ conf, float* __restrict__ out) {
    __shared__ unsigned sel[EQCAP];
    __shared__ float s_neg;
    int tid = threadIdx.x;
    int lane = tid & 31;
    int warp = tid >> 5;
    if (tid == 0) s_neg = 0.f;
    __syncthreads();

    unsigned take = g_takeAll ? 0u : g_take;
    unsigned E = min(g_eqcnt, (unsigned)EQCAP);
    if (take > 0) {
        for (unsigned j = tid; j < E; j += 1024) {
            unsigned long long vj = g_eq[j];
            unsigned rank = 0;
            for (unsigned l = 0; l < E; l++) rank += (g_eq[l] > vj) ? 1u : 0u;
            if (rank < take) sel[rank] = ~(unsigned)(vj & 0xFFFFFFFFull);
        }
    }
    __syncthreads();
    unsigned nsel = min(take, E);
    float accN = 0.f;
    for (unsigned i = warp; i < nsel; i += 32) {
        int row = (int)sel[i];
        float c0;
        float lse = warp_lse(conf + (size_t)row * NCLS, lane, c0);
        if (lane == 0) accN += lse - c0;
    }
    if (lane == 0 && accN != 0.f) atomicAdd(&s_neg, accN);
    __syncthreads();
    if (tid == 0) {
        unsigned np = g_numpos;
        unsigned keep = np + g_negcnt + nsel;
        out[0] = g_sl1 / (float)max(np, 1u);
        out[1] = (g_cepos + g_cenegsum + s_neg) / (float)max(keep, 1u);
    }
}

// ---------------- launch ----------------
extern "C" void kernel_launch(void* const* d_in, const int* in_sizes, int n_in,
                              void* d_out, int out_size) {
    const float* loc    = (const float*)d_in[0];
    const float* conf   = (const float*)d_in[1];
    const float* priors = (const float*)d_in[2];
    const float* gtb    = (const float*)d_in[3];
    const int*   gtl    = (const int*)d_in[4];
    float* out = (float*)d_out;

    k_init<<<1, 256>>>();                                          // 1
    k_match<<<dim3((NPRI + 255) / 256, BATCH), 256>>>(priors, gtb);// 2
    k_clearhist<<<512, 256>>>();                                   // 3 (+force)
    k_bigpass<<<ROWS / CHUNK, CHUNK>>>(loc, conf, priors, gtb, gtl);// 4 (profiled)
    k_select<<<1, 256>>>();                                        // 5
    k_mine<<<MINEBLKS, 256>>>(conf);                               // 6
    k_final<<<1, 1024>>>(conf, out);                               // 7
}

// round 16
// speedup vs baseline: 2.6508x; 2.6508x over previous
#include <cuda_runtime.h>
#include <cstdint>

#define BATCH 8
#define NPRI 57744
#define NCLS 81
#define NOBJ 20
#define ROWS (BATCH * NPRI)   // 461952 = 128 * 3609
#define NBINS (1u << 20)
#define EQCAP 8192
#define MINEBLKS 226

#define NEGINF __int_as_float(0xff800000)

// ---------------- device scratch ----------------
__device__ unsigned long long g_bestPrior[BATCH * NOBJ];
__device__ float2   g_match[ROWS];        // (best overlap, __int_as_float(best idx))
__device__ unsigned g_keys[ROWS];
__device__ unsigned g_posList[ROWS];      // (ct<<20)|row
__device__ unsigned long long g_eq[EQCAP];// (key<<32)|~row
__device__ unsigned g_hist[NBINS];        // 4 MB, 20-bit key histogram
__device__ unsigned g_segSum[256];
__device__ float    g_sl1, g_cepos, g_cenegsum;
__device__ unsigned g_numpos, g_negcnt, g_bhi, g_take, g_takeAll, g_eqcnt;

// ---------------- helpers ----------------
__device__ __forceinline__ float wmaxf(float v) {
    #pragma unroll
    for (int o = 16; o; o >>= 1) v = fmaxf(v, __shfl_xor_sync(0xffffffffu, v, o));
    return v;
}
__device__ __forceinline__ float wsumf(float v) {
    #pragma unroll
    for (int o = 16; o; o >>= 1) v += __shfl_xor_sync(0xffffffffu, v, o);
    return v;
}
__device__ __forceinline__ unsigned f2key(float f) {
    unsigned u = __float_as_uint(f);
    return (u & 0x80000000u) ? ~u : (u | 0x80000000u);
}
__device__ __forceinline__ float warp_lse(const float* __restrict__ cr, int lane,
                                          float& v0_lane0) {
    float v0 = cr[lane];
    float v1 = cr[lane + 32];
    float v2 = (lane < 17) ? cr[lane + 64] : NEGINF;
    float mAll = wmaxf(fmaxf(fmaxf(v0, v1), v2));
    float e2 = __expf(v0 - mAll) + __expf(v1 - mAll) +
               ((lane < 17) ? __expf(v2 - mAll) : 0.f);
    v0_lane0 = __shfl_sync(0xffffffffu, v0, 0);
    return mAll + __logf(wsumf(e2));
}

// ---------------- kernels ----------------
// launch 1: clear 4MB histogram + bestPrior + scalars (512 blocks x 256)
__global__ void k_init() {
    unsigned gid = blockIdx.x * blockDim.x + threadIdx.x;
    uint4 z = {0u, 0u, 0u, 0u};
    uint4* h4 = (uint4*)g_hist;
    #pragma unroll
    for (int j = 0; j < 2; j++) {
        unsigned i = gid + j * 131072u;
        if (i < NBINS / 4) h4[i] = z;
    }
    if (gid < BATCH * NOBJ) g_bestPrior[gid] = 0ull;
    if (gid == 0) {
        g_sl1 = 0.f; g_cepos = 0.f; g_cenegsum = 0.f;
        g_numpos = 0u; g_negcnt = 0u; g_bhi = 0u;
        g_take = 0u; g_takeAll = 0u; g_eqcnt = 0u;
    }
}

// per-GT best prior AND per-prior (overlap, idx) packed store
__global__ void k_match(const float* __restrict__ priors,
                        const float* __restrict__ gt_boxes) {
    int b = blockIdx.y;
    int p = blockIdx.x * blockDim.x + threadIdx.x;
    __shared__ float4 sgt[NOBJ];
    __shared__ float  sga[NOBJ];
    __shared__ unsigned long long sbest[NOBJ];
    if (threadIdx.x < NOBJ) {
        float4 g = ((const float4*)gt_boxes)[b * NOBJ + threadIdx.x];
        sgt[threadIdx.x] = g;
        sga[threadIdx.x] = (g.z - g.x) * (g.w - g.y);
        sbest[threadIdx.x] = 0ull;
    }
    __syncthreads();

    if (p < NPRI) {
        float4 pr = ((const float4*)priors)[p];
        float px1 = pr.x - pr.z * 0.5f, py1 = pr.y - pr.w * 0.5f;
        float px2 = pr.x + pr.z * 0.5f, py2 = pr.y + pr.w * 0.5f;
        float pa = pr.z * pr.w;
        float bestOv = -1.f; int bestN = 0;
        #pragma unroll
        for (int n = 0; n < NOBJ; n++) {
            float4 g = sgt[n];
            float ix = fmaxf(fminf(px2, g.z) - fmaxf(px1, g.x), 0.f);
            float iy = fmaxf(fminf(py2, g.w) - fmaxf(py1, g.y), 0.f);
            float inter = ix * iy;
            float iou = inter / (pa + sga[n] - inter);
            if (iou > bestOv) { bestOv = iou; bestN = n; }
            if (iou > 0.f) {
                unsigned long long k =
                    (((unsigned long long)__float_as_uint(iou)) << 32) |
                    (unsigned long long)(~(unsigned)p);
                if (k > sbest[n]) atomicMax(&sbest[n], k);
            }
        }
        g_match[b * NPRI + p] = make_float2(bestOv, __int_as_float(bestN));
    }
    __syncthreads();
    if (threadIdx.x < NOBJ && sbest[threadIdx.x])
        atomicMax(&g_bestPrior[b * NOBJ + threadIdx.x], sbest[threadIdx.x]);
}

// launch 3: tiny force-match (sequential per batch, last n wins)
__global__ void k_force() {
    int b = threadIdx.x;
    if (b >= BATCH) return;
    for (int n = 0; n < NOBJ; n++) {
        unsigned long long v = g_bestPrior[b * NOBJ + n];
        unsigned p = (v == 0ull) ? 0u : ~(unsigned)(v & 0xFFFFFFFFull);
        g_match[b * NPRI + p] = make_float2(2.0f, __int_as_float(n));
    }
}

// 128 threads = 128 rows; conf staged via cp.async; match results loaded
__global__ void __launch_bounds__(128)
k_bigpass(const float* __restrict__ loc_data,
          const float* __restrict__ conf,
          const float* __restrict__ priors,
          const float* __restrict__ gt_boxes,
          const int*   __restrict__ gt_labels) {
    __shared__ float s[128 * NCLS];           // 41472 B
    int tid = threadIdx.x;
    int S = blockIdx.x * 128;
    int row = S + tid;

    const float4* c4 = (const float4*)conf + (size_t)S * NCLS / 4;
    unsigned sbase = (unsigned)__cvta_generic_to_shared(s);
    int i = tid;
    #pragma unroll
    for (int k = 0; k < 20; k++, i += 128)
        asm volatile("cp.async.cg.shared.global [%0], [%1], 16;"
                     :: "r"(sbase + i * 16), "l"(c4 + i));
    if (i < (128 * NCLS / 4))
        asm volatile("cp.async.cg.shared.global [%0], [%1], 16;"
                     :: "r"(sbase + i * 16), "l"(c4 + i));
    asm volatile("cp.async.commit_group;");

    // prefetch match result (single 8B load) while cp.async streams
    float2 mv = g_match[row];
    float ov = mv.x;
    int   n  = __float_as_int(mv.y);

    asm volatile("cp.async.wait_group 0;");
    __syncthreads();

    const float* rp = s + tid * NCLS;
    float m0 = rp[1], m1 = rp[2], m2 = rp[3], m3 = rp[4];
    #pragma unroll
    for (int c = 5; c <= 77; c += 4) {     // ILP-4 fmax, classes 1..80
        m0 = fmaxf(m0, rp[c]);
        m1 = fmaxf(m1, rp[c + 1]);
        m2 = fmaxf(m2, rp[c + 2]);
        m3 = fmaxf(m3, rp[c + 3]);
    }
    float m = fmaxf(fmaxf(m0, m1), fmaxf(m2, m3));

    int b = row / NPRI;
    int ct;
    if (ov < 0.4f) ct = 0;
    else if (ov < 0.5f) ct = -1;
    else ct = gt_labels[b * NOBJ + n];     // rare path, direct gmem

    unsigned key = 0u;
    if (ct == 0) { key = f2key(m); if (!key) key = 1u; }
    g_keys[row] = key;

    // warp-aggregated histogram update (reduce L2 atomic contention)
    {
        unsigned bin = key ? (key >> 12) : 0xFFFFFFFFu;
        unsigned peers = __match_any_sync(0xffffffffu, bin);
        if (key) {
            int leader = __ffs(peers) - 1;
            if ((tid & 31) == leader)
                atomicAdd(&g_hist[bin], (unsigned)__popc(peers));
        }
    }

    if (ct > 0) {   // rare
        int p = row - b * NPRI;
        float4 pr = ((const float4*)priors)[p];
        float4 g  = ((const float4*)gt_boxes)[b * NOBJ + n];
        float lt[4];
        lt[0] = ((g.x + g.z) * 0.5f - pr.x) / (0.1f * pr.z);
        lt[1] = ((g.y + g.w) * 0.5f - pr.y) / (0.1f * pr.w);
        lt[2] = logf((g.z - g.x) / pr.z) / 0.2f;
        lt[3] = logf((g.w - g.y) / pr.w) / 0.2f;
        const float* ld = loc_data + (size_t)row * 4;
        float sl = 0.f;
        #pragma unroll
        for (int q = 0; q < 4; q++) {
            float d = ld[q] - lt[q];
            float a = fabsf(d);
            sl += (a < 1.f) ? 0.5f * d * d : a - 0.5f;
        }
        atomicAdd(&g_sl1, sl);
        unsigned slot = atomicAdd(&g_numpos, 1u);
        g_posList[slot] = ((unsigned)ct << 20) | (unsigned)row;
    }
}

// 256 blocks, each sums a descending 4096-bin segment
__global__ void k_selectA() {
    int b = blockIdx.x;
    int t = threadIdx.x;
    unsigned base = NBINS - (unsigned)(b + 1) * 4096u;
    unsigned s = 0;
    #pragma unroll
    for (int j = 0; j < 16; j++) s += g_hist[base + j * 256 + t];
    __shared__ unsigned red[256];
    red[t] = s; __syncthreads();
    for (int off = 128; off; off >>= 1) {
        if (t < off) red[t] += red[t + off];
        __syncthreads();
    }
    if (t == 0) g_segSum[b] = red[0];
}

__global__ void k_selectB() {
    __shared__ unsigned part[256];
    __shared__ unsigned sSeg, sR0;
    int t = threadIdx.x;
    unsigned v = g_segSum[t];
    part[t] = v; __syncthreads();
    for (int off = 1; off < 256; off <<= 1) {
        unsigned add = (t >= off) ? part[t - off] : 0u;
        __syncthreads(); part[t] += add; __syncthreads();
    }
    unsigned total = part[255];
    unsigned K = 3u * g_numpos;
    if (K == 0u) { if (t == 0) { g_bhi = NBINS; g_take = 0u; } return; }
    if (total <= K) {
        if (t == 0) { g_takeAll = 1u; g_bhi = NBINS; g_take = 0u; }
        return;
    }
    unsigned incl = part[t], excl = incl - v;
    if (excl < K && K <= incl) { sSeg = (unsigned)t; sR0 = K - excl; }
    __syncthreads();
    unsigned seg = sSeg, r0 = sR0;
    unsigned top = NBINS - seg * 4096u - 1u;
    unsigned cnt[16], cs = 0;
    #pragma unroll
    for (int j = 0; j < 16; j++) { cnt[j] = g_hist[top - (t * 16 + j)]; cs += cnt[j]; }
    part[t] = cs; __syncthreads();
    for (int off = 1; off < 256; off <<= 1) {
        unsigned add = (t >= off) ? part[t - off] : 0u;
        __syncthreads(); part[t] += add; __syncthreads();
    }
    unsigned incl2 = part[t], excl2 = incl2 - cs;
    if (excl2 < r0 && r0 <= incl2) {
        unsigned cum = excl2;
        #pragma unroll
        for (int j = 0; j < 16; j++) {
            if (r0 <= cum + cnt[j]) {
                g_bhi = top - (t * 16 + j);
                g_take = r0 - cum;
                break;
            }
            cum += cnt[j];
        }
    }
}

// fused: scan keys, compute neg CE for clear winners, collect boundary,
// plus pos CE (grid-strided)
__global__ void __launch_bounds__(256)
k_mine(const float* __restrict__ conf) {
    __shared__ unsigned list[2048];
    __shared__ unsigned s_cnt;
    __shared__ float s_neg, s_pos;
    int tid = threadIdx.x;
    int lane = tid & 31;
    int warp = tid >> 5;
    if (tid == 0) { s_cnt = 0u; s_neg = 0.f; s_pos = 0.f; }
    __syncthreads();

    unsigned takeAll = g_takeAll;
    unsigned bhi = g_bhi;
    int base = blockIdx.x * 2048;
    #pragma unroll
    for (int j = 0; j < 8; j++) {
        int i = base + j * 256 + tid;
        if (i < ROWS) {
            unsigned key = g_keys[i];
            if (key) {
                unsigned bin = key >> 12;
                if (takeAll || bin > bhi) {
                    unsigned slot = atomicAdd(&s_cnt, 1u);
                    list[slot] = (unsigned)i;
                } else if (bin == bhi) {
                    unsigned slot = atomicAdd(&g_eqcnt, 1u);
                    if (slot < EQCAP)
                        g_eq[slot] = (((unsigned long long)key) << 32) |
                                     (unsigned long long)(~(unsigned)i);
                }
            }
        }
    }
    __syncthreads();

    unsigned cnt = s_cnt;
    float accN = 0.f;
    for (unsigned li = warp; li < cnt; li += 8) {
        int row = (int)list[li];
        float c0;
        float lse = warp_lse(conf + (size_t)row * NCLS, lane, c0);
        if (lane == 0) accN += lse - c0;
    }

    unsigned np = g_numpos;
    float accP = 0.f;
    for (unsigned i = blockIdx.x * 8 + warp; i < np; i += MINEBLKS * 8) {
        unsigned e = g_posList[i];
        int row = (int)(e & 0xFFFFFu);
        int ct  = (int)(e >> 20);
        const float* cr = conf + (size_t)row * NCLS;
        float v0 = cr[lane];
        float v1 = cr[lane + 32];
        float v2 = (lane < 17) ? cr[lane + 64] : NEGINF;
        float mAll = wmaxf(fmaxf(fmaxf(v0, v1), v2));
        float e2 = __expf(v0 - mAll) + __expf(v1 - mAll) +
                   ((lane < 17) ? __expf(v2 - mAll) : 0.f);
        float lse = mAll + __logf(wsumf(e2));
        float x = NEGINF;
        if (lane == ct) x = v0;
        if (lane + 32 == ct) x = v1;
        if (lane < 17 && lane + 64 == ct) x = v2;
        x = wmaxf(x);
        if (lane == 0) accP += lse - x;
    }
    if (lane == 0) {
        if (accN != 0.f) atomicAdd(&s_neg, accN);
        if (accP != 0.f) atomicAdd(&s_pos, accP);
    }
    __syncthreads();
    if (tid == 0) {
        if (cnt) atomicAdd(&g_negcnt, cnt);
        if (s_neg != 0.f) atomicAdd(&g_cenegsum, s_neg);
        if (s_pos != 0.f) atomicAdd(&g_cepos, s_pos);
    }
}

// one block: exact boundary resolution + CE of chosen boundary rows + outputs
__global__ void __launch_bounds__(1024)
k_final(const float* __restrict__ conf, float* __restrict__ out) {
    __shared__ unsigned sel[EQCAP];
    __shared__ float s_neg;
    int tid = threadIdx.x;
    int lane = tid & 31;
    int warp = tid >> 5;
    if (tid == 0) s_neg = 0.f;
    __syncthreads();

    unsigned take = g_takeAll ? 0u : g_take;
    unsigned E = min(g_eqcnt, (unsigned)EQCAP);
    if (take > 0) {
        for (unsigned j = tid; j < E; j += 1024) {
            unsigned long long vj = g_eq[j];
            unsigned rank = 0;
            for (unsigned l = 0; l < E; l++) rank += (g_eq[l] > vj) ? 1u : 0u;
            if (rank < take) sel[rank] = ~(unsigned)(vj & 0xFFFFFFFFull);
        }
    }
    __syncthreads();
    unsigned nsel = min(take, E);
    float accN = 0.f;
    for (unsigned i = warp; i < nsel; i += 32) {
        int row = (int)sel[i];
        float c0;
        float lse = warp_lse(conf + (size_t)row * NCLS, lane, c0);
        if (lane == 0) accN += lse - c0;
    }
    if (lane == 0 && accN != 0.f) atomicAdd(&s_neg, accN);
    __syncthreads();
    if (tid == 0) {
        unsigned np = g_numpos;
        unsigned keep = np + g_negcnt + nsel;
        out[0] = g_sl1 / (float)max(np, 1u);
        out[1] = (g_cepos + g_cenegsum + s_neg) / (float)max(keep, 1u);
    }
}

// ---------------- launch ----------------
extern "C" void kernel_launch(void* const* d_in, const int* in_sizes, int n_in,
                              void* d_out, int out_size) {
    const float* loc    = (const float*)d_in[0];
    const float* conf   = (const float*)d_in[1];
    const float* priors = (const float*)d_in[2];
    const float* gtb    = (const float*)d_in[3];
    const int*   gtl    = (const int*)d_in[4];
    float* out = (float*)d_out;

    k_init<<<512, 256>>>();                                        // 1 (clear+init)
    k_match<<<dim3((NPRI + 255) / 256, BATCH), 256>>>(priors, gtb);// 2
    k_force<<<1, 32>>>();                                          // 3
    k_bigpass<<<ROWS / 128, 128>>>(loc, conf, priors, gtb, gtl);   // 4 (profiled)
    k_selectA<<<256, 256>>>();                                     // 5
    k_selectB<<<1, 256>>>();                                       // 6
    k_mine<<<MINEBLKS, 256>>>(conf);                               // 7
    k_final<<<1, 1024>>>(conf, out);                               // 8
}